// round 1
// baseline (speedup 1.0000x reference)
#include <cuda_runtime.h>
#include <cstddef>

#define D_MODEL 1024
#define HEADS   16
#define D_K     64
#define BATCH   2
#define SEQ     2048
#define M_TOTAL (BATCH * SEQ)   // 4096

// Scratch (allocation-free rule: __device__ globals)
__device__ float g_Q[M_TOTAL * D_MODEL];
__device__ float g_K[M_TOTAL * D_MODEL];
__device__ float g_V[M_TOTAL * D_MODEL];
__device__ float g_ctx[M_TOTAL * D_MODEL];

// ---------------------------------------------------------------------------
// SGEMM (NT): C[M,N] = A[M,K] * W[N,K]^T + bias[N]
// 128x128 tile, BK=16, 256 threads, 8x8 per-thread microtile.
// ---------------------------------------------------------------------------
__global__ __launch_bounds__(256)
void sgemm_nt_bias(const float* __restrict__ A,
                   const float* __restrict__ W,
                   const float* __restrict__ bias,
                   float* __restrict__ C,
                   int M, int N, int K)
{
    constexpr int BM = 128, BN = 128, BK = 16, TM = 8, TN = 8;
    __shared__ float As[BK][BM];
    __shared__ float Bs[BK][BN];

    const int tid  = threadIdx.x;
    const int tcol = tid & 15;   // 0..15
    const int trow = tid >> 4;   // 0..15
    const int rowBase = blockIdx.y * BM;
    const int colBase = blockIdx.x * BN;

    // tile-load indexing: 512 float4 per operand tile, 2 per thread
    const int ldRow = tid >> 2;  // 0..63 (plus +64 second pass)
    const int ldK4  = tid & 3;   // which float4 along k

    float acc[TM][TN];
    #pragma unroll
    for (int i = 0; i < TM; i++)
        #pragma unroll
        for (int j = 0; j < TN; j++) acc[i][j] = 0.f;

    for (int kt = 0; kt < K; kt += BK) {
        #pragma unroll
        for (int p = 0; p < 2; p++) {
            int r = ldRow + p * 64;
            float4 va = *reinterpret_cast<const float4*>(
                &A[(size_t)(rowBase + r) * K + kt + ldK4 * 4]);
            As[ldK4 * 4 + 0][r] = va.x;
            As[ldK4 * 4 + 1][r] = va.y;
            As[ldK4 * 4 + 2][r] = va.z;
            As[ldK4 * 4 + 3][r] = va.w;
            float4 vb = *reinterpret_cast<const float4*>(
                &W[(size_t)(colBase + r) * K + kt + ldK4 * 4]);
            Bs[ldK4 * 4 + 0][r] = vb.x;
            Bs[ldK4 * 4 + 1][r] = vb.y;
            Bs[ldK4 * 4 + 2][r] = vb.z;
            Bs[ldK4 * 4 + 3][r] = vb.w;
        }
        __syncthreads();

        #pragma unroll
        for (int kk = 0; kk < BK; kk++) {
            float ra[TM], rb[TN];
            #pragma unroll
            for (int i = 0; i < TM; i += 4) {
                float4 v = *reinterpret_cast<const float4*>(&As[kk][trow * TM + i]);
                ra[i] = v.x; ra[i + 1] = v.y; ra[i + 2] = v.z; ra[i + 3] = v.w;
            }
            #pragma unroll
            for (int j = 0; j < TN; j += 4) {
                float4 v = *reinterpret_cast<const float4*>(&Bs[kk][tcol * TN + j]);
                rb[j] = v.x; rb[j + 1] = v.y; rb[j + 2] = v.z; rb[j + 3] = v.w;
            }
            #pragma unroll
            for (int i = 0; i < TM; i++)
                #pragma unroll
                for (int j = 0; j < TN; j++)
                    acc[i][j] += ra[i] * rb[j];
        }
        __syncthreads();
    }

    // epilogue: + bias, vectorized stores
    #pragma unroll
    for (int i = 0; i < TM; i++) {
        int row = rowBase + trow * TM + i;
        #pragma unroll
        for (int j = 0; j < TN; j += 4) {
            int col = colBase + tcol * TN + j;
            float4 o;
            o.x = acc[i][j + 0] + bias[col + 0];
            o.y = acc[i][j + 1] + bias[col + 1];
            o.z = acc[i][j + 2] + bias[col + 2];
            o.w = acc[i][j + 3] + bias[col + 3];
            *reinterpret_cast<float4*>(&C[(size_t)row * N + col]) = o;
        }
    }
}

// ---------------------------------------------------------------------------
// Causal flash attention, fp32. 1 thread = 1 query row.
// BQ=128 queries per block (128 threads), K/V tiles of 64 keys in smem.
// Q (pre-scaled by 1/sqrt(Dk)) and O accumulator live in registers.
// ---------------------------------------------------------------------------
#define BQ  128
#define BKV 64

__global__ __launch_bounds__(BQ)
void flash_attn_causal(const float* __restrict__ Qg,
                       const float* __restrict__ Kg,
                       const float* __restrict__ Vg,
                       float* __restrict__ Og)
{
    const int h = blockIdx.y;
    const int b = blockIdx.z;
    const int qg = blockIdx.x * BQ + threadIdx.x;   // query row in sequence

    const float* Qb = Qg + (size_t)b * SEQ * D_MODEL + h * D_K;
    const float* Kb = Kg + (size_t)b * SEQ * D_MODEL + h * D_K;
    const float* Vb = Vg + (size_t)b * SEQ * D_MODEL + h * D_K;
    float*       Ob = Og + (size_t)b * SEQ * D_MODEL + h * D_K;

    __shared__ float Ks[BKV][D_K];
    __shared__ float Vs[BKV][D_K];

    float q[D_K], o[D_K];
    #pragma unroll
    for (int d = 0; d < D_K; d++) {
        q[d] = Qb[(size_t)qg * D_MODEL + d] * 0.125f;  // 1/sqrt(64)
        o[d] = 0.f;
    }
    float m = -1e30f, l = 0.f;

    const int kend = blockIdx.x * BQ + BQ;  // causal: only keys <= last query of tile

    for (int kt = 0; kt < kend; kt += BKV) {
        // cooperative tile load: 1024 float4 per operand, 8 per thread
        #pragma unroll
        for (int i = 0; i < 8; i++) {
            int idx = threadIdx.x + i * BQ;       // 0..1023
            int r   = idx >> 4;                    // key row within tile
            int d4  = idx & 15;                    // float4 within row
            reinterpret_cast<float4*>(&Ks[0][0])[idx] =
                *reinterpret_cast<const float4*>(&Kb[(size_t)(kt + r) * D_MODEL + d4 * 4]);
            reinterpret_cast<float4*>(&Vs[0][0])[idx] =
                *reinterpret_cast<const float4*>(&Vb[(size_t)(kt + r) * D_MODEL + d4 * 4]);
        }
        __syncthreads();

        #pragma unroll 1
        for (int c = 0; c < BKV; c += 16) {
            if (kt + c <= qg) {  // chunk has at least one unmasked key for this row
                float s[16];
                #pragma unroll
                for (int j = 0; j < 16; j++) {
                    const float4* kr = reinterpret_cast<const float4*>(&Ks[c + j][0]);
                    float a0 = 0.f, a1 = 0.f, a2 = 0.f, a3 = 0.f;
                    #pragma unroll
                    for (int d4 = 0; d4 < 16; d4 += 4) {
                        float4 k0 = kr[d4 + 0];
                        float4 k1 = kr[d4 + 1];
                        float4 k2 = kr[d4 + 2];
                        float4 k3 = kr[d4 + 3];
                        a0 += q[(d4+0)*4+0]*k0.x + q[(d4+0)*4+1]*k0.y + q[(d4+0)*4+2]*k0.z + q[(d4+0)*4+3]*k0.w;
                        a1 += q[(d4+1)*4+0]*k1.x + q[(d4+1)*4+1]*k1.y + q[(d4+1)*4+2]*k1.z + q[(d4+1)*4+3]*k1.w;
                        a2 += q[(d4+2)*4+0]*k2.x + q[(d4+2)*4+1]*k2.y + q[(d4+2)*4+2]*k2.z + q[(d4+2)*4+3]*k2.w;
                        a3 += q[(d4+3)*4+0]*k3.x + q[(d4+3)*4+1]*k3.y + q[(d4+3)*4+2]*k3.z + q[(d4+3)*4+3]*k3.w;
                    }
                    float acc = (a0 + a1) + (a2 + a3);
                    s[j] = (kt + c + j <= qg) ? acc : -1e30f;
                }
                float tmax = s[0];
                #pragma unroll
                for (int j = 1; j < 16; j++) tmax = fmaxf(tmax, s[j]);
                float mnew = fmaxf(m, tmax);
                float corr = __expf(m - mnew);
                l *= corr;
                #pragma unroll
                for (int d = 0; d < D_K; d++) o[d] *= corr;
                m = mnew;
                #pragma unroll
                for (int j = 0; j < 16; j++) {
                    float p = __expf(s[j] - mnew);
                    l += p;
                    const float4* vr = reinterpret_cast<const float4*>(&Vs[c + j][0]);
                    #pragma unroll
                    for (int d4 = 0; d4 < 16; d4++) {
                        float4 vv = vr[d4];
                        o[d4 * 4 + 0] += p * vv.x;
                        o[d4 * 4 + 1] += p * vv.y;
                        o[d4 * 4 + 2] += p * vv.z;
                        o[d4 * 4 + 3] += p * vv.w;
                    }
                }
            }
        }
        __syncthreads();
    }

    float inv = 1.f / l;
    #pragma unroll
    for (int d = 0; d < D_K; d += 4) {
        float4 out;
        out.x = o[d + 0] * inv;
        out.y = o[d + 1] * inv;
        out.z = o[d + 2] * inv;
        out.w = o[d + 3] * inv;
        *reinterpret_cast<float4*>(&Ob[(size_t)qg * D_MODEL + d]) = out;
    }
}

// ---------------------------------------------------------------------------
// Launch
// ---------------------------------------------------------------------------
extern "C" void kernel_launch(void* const* d_in, const int* in_sizes, int n_in,
                              void* d_out, int out_size)
{
    (void)in_sizes; (void)n_in; (void)out_size;
    const float* q    = (const float*)d_in[0];
    const float* k    = (const float*)d_in[1];
    const float* v    = (const float*)d_in[2];
    // d_in[3] = mask (causal tril) — implemented analytically
    const float* wq_w = (const float*)d_in[4];
    const float* wq_b = (const float*)d_in[5];
    const float* wk_w = (const float*)d_in[6];
    const float* wk_b = (const float*)d_in[7];
    const float* wv_w = (const float*)d_in[8];
    const float* wv_b = (const float*)d_in[9];
    const float* wo_w = (const float*)d_in[10];
    const float* wo_b = (const float*)d_in[11];
    float* out = (float*)d_out;

    void *pQ, *pK, *pV, *pC;
    cudaGetSymbolAddress(&pQ, g_Q);
    cudaGetSymbolAddress(&pK, g_K);
    cudaGetSymbolAddress(&pV, g_V);
    cudaGetSymbolAddress(&pC, g_ctx);
    float* Qp = (float*)pQ;
    float* Kp = (float*)pK;
    float* Vp = (float*)pV;
    float* Cp = (float*)pC;

    dim3 gemmGrid(D_MODEL / 128, M_TOTAL / 128);  // (8, 32)
    sgemm_nt_bias<<<gemmGrid, 256>>>(q, wq_w, wq_b, Qp, M_TOTAL, D_MODEL, D_MODEL);
    sgemm_nt_bias<<<gemmGrid, 256>>>(k, wk_w, wk_b, Kp, M_TOTAL, D_MODEL, D_MODEL);
    sgemm_nt_bias<<<gemmGrid, 256>>>(v, wv_w, wv_b, Vp, M_TOTAL, D_MODEL, D_MODEL);

    dim3 attnGrid(SEQ / BQ, HEADS, BATCH);        // (16, 16, 2)
    flash_attn_causal<<<attnGrid, BQ>>>(Qp, Kp, Vp, Cp);

    sgemm_nt_bias<<<gemmGrid, 256>>>(Cp, wo_w, wo_b, out, M_TOTAL, D_MODEL, D_MODEL);
}

// round 3
// speedup vs baseline: 1.5624x; 1.5624x over previous
#include <cuda_runtime.h>
#include <cstdint>
#include <cstddef>

#define D_MODEL 1024
#define HEADS   16
#define D_K     64
#define BATCH   2
#define SEQ     2048
#define M_TOTAL (BATCH * SEQ)   // 4096

// Scratch (allocation-free rule: __device__ globals)
__device__ float g_Q[M_TOTAL * D_MODEL];
__device__ float g_K[M_TOTAL * D_MODEL];
__device__ float g_V[M_TOTAL * D_MODEL];
__device__ float g_ctx[M_TOTAL * D_MODEL];

// ---------------------------------------------------------------------------
// tf32 helpers (baseline PTX, legal on compute_103)
// ---------------------------------------------------------------------------
__device__ __forceinline__ float tf32_rna(float x) {
    uint32_t r;
    asm("cvt.rna.tf32.f32 %0, %1;" : "=r"(r) : "f"(x));
    return __uint_as_float(r);
}

__device__ __forceinline__ void mma_tf32_16x8x8(
    float& d0, float& d1, float& d2, float& d3,
    uint32_t a0, uint32_t a1, uint32_t a2, uint32_t a3,
    uint32_t b0, uint32_t b1)
{
    asm volatile(
        "mma.sync.aligned.m16n8k8.row.col.f32.tf32.tf32.f32 "
        "{%0,%1,%2,%3}, {%4,%5,%6,%7}, {%8,%9}, {%0,%1,%2,%3};"
        : "+f"(d0), "+f"(d1), "+f"(d2), "+f"(d3)
        : "r"(a0), "r"(a1), "r"(a2), "r"(a3), "r"(b0), "r"(b1));
}

// ---------------------------------------------------------------------------
// tf32 mma.sync GEMM (NT + bias): C[M,N] = A[M,K] * W[N,K]^T + bias[N]
// 128x128 CTA tile, BK=32, 256 threads (8 warps, 2x4 grid), 64x32 warp tile.
// grid = (N/128, M/128).
// ---------------------------------------------------------------------------
#define BM  128
#define BN  128
#define BKG 32
#define PAD 4
#define LDP (BKG + PAD)   // smem row pitch in floats = 36

__global__ __launch_bounds__(256, 2)
void gemm_tf32_mma(const float* __restrict__ A,
                   const float* __restrict__ W,
                   const float* __restrict__ bias,
                   float* __restrict__ C,
                   int M, int N, int K)
{
    __shared__ float As[BM][LDP];
    __shared__ float Bs[BN][LDP];

    const int tid  = threadIdx.x;
    const int wid  = tid >> 5;
    const int lane = tid & 31;
    const int wm = wid & 1;       // 0..1
    const int wn = wid >> 1;      // 0..3
    const int rowBase = blockIdx.y * BM;
    const int colBase = blockIdx.x * BN;
    const int warpRow = wm * 64;
    const int warpCol = wn * 32;

    const int ldr  = tid >> 3;    // 0..31 (row step of 32 per pass)
    const int ldc4 = tid & 7;     // float4 index along k

    float acc[4][4][4];
    #pragma unroll
    for (int mt = 0; mt < 4; mt++)
        #pragma unroll
        for (int nt = 0; nt < 4; nt++)
            #pragma unroll
            for (int i = 0; i < 4; i++) acc[mt][nt][i] = 0.f;

    float4 pa[4], pb[4];

    // prefetch tile kt=0
    #pragma unroll
    for (int i = 0; i < 4; i++) {
        int r = ldr + i * 32;
        pa[i] = *reinterpret_cast<const float4*>(&A[(size_t)(rowBase + r) * K + ldc4 * 4]);
        pb[i] = *reinterpret_cast<const float4*>(&W[(size_t)(colBase + r) * K + ldc4 * 4]);
    }
    #pragma unroll
    for (int i = 0; i < 4; i++) {
        int r = ldr + i * 32;
        float4 va = pa[i], vb = pb[i];
        As[r][ldc4*4+0] = tf32_rna(va.x); As[r][ldc4*4+1] = tf32_rna(va.y);
        As[r][ldc4*4+2] = tf32_rna(va.z); As[r][ldc4*4+3] = tf32_rna(va.w);
        Bs[r][ldc4*4+0] = tf32_rna(vb.x); Bs[r][ldc4*4+1] = tf32_rna(vb.y);
        Bs[r][ldc4*4+2] = tf32_rna(vb.z); Bs[r][ldc4*4+3] = tf32_rna(vb.w);
    }
    __syncthreads();

    for (int kt = 0; kt < K; kt += BKG) {
        if (kt + BKG < K) {
            #pragma unroll
            for (int i = 0; i < 4; i++) {
                int r = ldr + i * 32;
                pa[i] = *reinterpret_cast<const float4*>(
                    &A[(size_t)(rowBase + r) * K + kt + BKG + ldc4 * 4]);
                pb[i] = *reinterpret_cast<const float4*>(
                    &W[(size_t)(colBase + r) * K + kt + BKG + ldc4 * 4]);
            }
        }

        #pragma unroll
        for (int kk = 0; kk < BKG; kk += 8) {
            const int r0 = warpRow + (lane >> 2);
            const int n0 = warpCol + (lane >> 2);
            const int kA = kk + (lane & 3);
            uint32_t af[4][4], bf[4][2];
            #pragma unroll
            for (int mt = 0; mt < 4; mt++) {
                af[mt][0] = __float_as_uint(As[r0 + mt*16    ][kA    ]);
                af[mt][1] = __float_as_uint(As[r0 + mt*16 + 8][kA    ]);
                af[mt][2] = __float_as_uint(As[r0 + mt*16    ][kA + 4]);
                af[mt][3] = __float_as_uint(As[r0 + mt*16 + 8][kA + 4]);
            }
            #pragma unroll
            for (int nt = 0; nt < 4; nt++) {
                bf[nt][0] = __float_as_uint(Bs[n0 + nt*8][kA    ]);
                bf[nt][1] = __float_as_uint(Bs[n0 + nt*8][kA + 4]);
            }
            #pragma unroll
            for (int mt = 0; mt < 4; mt++)
                #pragma unroll
                for (int nt = 0; nt < 4; nt++)
                    mma_tf32_16x8x8(acc[mt][nt][0], acc[mt][nt][1],
                                    acc[mt][nt][2], acc[mt][nt][3],
                                    af[mt][0], af[mt][1], af[mt][2], af[mt][3],
                                    bf[nt][0], bf[nt][1]);
        }
        __syncthreads();

        if (kt + BKG < K) {
            #pragma unroll
            for (int i = 0; i < 4; i++) {
                int r = ldr + i * 32;
                float4 va = pa[i], vb = pb[i];
                As[r][ldc4*4+0] = tf32_rna(va.x); As[r][ldc4*4+1] = tf32_rna(va.y);
                As[r][ldc4*4+2] = tf32_rna(va.z); As[r][ldc4*4+3] = tf32_rna(va.w);
                Bs[r][ldc4*4+0] = tf32_rna(vb.x); Bs[r][ldc4*4+1] = tf32_rna(vb.y);
                Bs[r][ldc4*4+2] = tf32_rna(vb.z); Bs[r][ldc4*4+3] = tf32_rna(vb.w);
            }
            __syncthreads();
        }
    }

    // epilogue: + bias, float2 stores (accumulator fragment layout)
    #pragma unroll
    for (int nt = 0; nt < 4; nt++) {
        const int col = colBase + warpCol + nt * 8 + 2 * (lane & 3);
        const float b0 = bias[col], b1 = bias[col + 1];
        #pragma unroll
        for (int mt = 0; mt < 4; mt++) {
            const int row = rowBase + warpRow + mt * 16 + (lane >> 2);
            float2 v0 = make_float2(acc[mt][nt][0] + b0, acc[mt][nt][1] + b1);
            float2 v1 = make_float2(acc[mt][nt][2] + b0, acc[mt][nt][3] + b1);
            *reinterpret_cast<float2*>(&C[(size_t)row * N + col])       = v0;
            *reinterpret_cast<float2*>(&C[(size_t)(row + 8) * N + col]) = v1;
        }
    }
}

// ---------------------------------------------------------------------------
// Causal flash attention, fp32 SIMT (unchanged — round 4 target).
// ---------------------------------------------------------------------------
#define BQ  128
#define BKV 64

__global__ __launch_bounds__(BQ)
void flash_attn_causal(const float* __restrict__ Qg,
                       const float* __restrict__ Kg,
                       const float* __restrict__ Vg,
                       float* __restrict__ Og)
{
    const int h = blockIdx.y;
    const int b = blockIdx.z;
    const int qg = blockIdx.x * BQ + threadIdx.x;

    const float* Qb = Qg + (size_t)b * SEQ * D_MODEL + h * D_K;
    const float* Kb = Kg + (size_t)b * SEQ * D_MODEL + h * D_K;
    const float* Vb = Vg + (size_t)b * SEQ * D_MODEL + h * D_K;
    float*       Ob = Og + (size_t)b * SEQ * D_MODEL + h * D_K;

    __shared__ float Ks[BKV][D_K];
    __shared__ float Vs[BKV][D_K];

    float q[D_K], o[D_K];
    #pragma unroll
    for (int d = 0; d < D_K; d++) {
        q[d] = Qb[(size_t)qg * D_MODEL + d] * 0.125f;
        o[d] = 0.f;
    }
    float m = -1e30f, l = 0.f;

    const int kend = blockIdx.x * BQ + BQ;

    for (int kt = 0; kt < kend; kt += BKV) {
        #pragma unroll
        for (int i = 0; i < 8; i++) {
            int idx = threadIdx.x + i * BQ;
            int r   = idx >> 4;
            int d4  = idx & 15;
            reinterpret_cast<float4*>(&Ks[0][0])[idx] =
                *reinterpret_cast<const float4*>(&Kb[(size_t)(kt + r) * D_MODEL + d4 * 4]);
            reinterpret_cast<float4*>(&Vs[0][0])[idx] =
                *reinterpret_cast<const float4*>(&Vb[(size_t)(kt + r) * D_MODEL + d4 * 4]);
        }
        __syncthreads();

        #pragma unroll 1
        for (int c = 0; c < BKV; c += 16) {
            if (kt + c <= qg) {
                float s[16];
                #pragma unroll
                for (int j = 0; j < 16; j++) {
                    const float4* kr = reinterpret_cast<const float4*>(&Ks[c + j][0]);
                    float a0 = 0.f, a1 = 0.f, a2 = 0.f, a3 = 0.f;
                    #pragma unroll
                    for (int d4 = 0; d4 < 16; d4 += 4) {
                        float4 k0 = kr[d4 + 0];
                        float4 k1 = kr[d4 + 1];
                        float4 k2 = kr[d4 + 2];
                        float4 k3 = kr[d4 + 3];
                        a0 += q[(d4+0)*4+0]*k0.x + q[(d4+0)*4+1]*k0.y + q[(d4+0)*4+2]*k0.z + q[(d4+0)*4+3]*k0.w;
                        a1 += q[(d4+1)*4+0]*k1.x + q[(d4+1)*4+1]*k1.y + q[(d4+1)*4+2]*k1.z + q[(d4+1)*4+3]*k1.w;
                        a2 += q[(d4+2)*4+0]*k2.x + q[(d4+2)*4+1]*k2.y + q[(d4+2)*4+2]*k2.z + q[(d4+2)*4+3]*k2.w;
                        a3 += q[(d4+3)*4+0]*k3.x + q[(d4+3)*4+1]*k3.y + q[(d4+3)*4+2]*k3.z + q[(d4+3)*4+3]*k3.w;
                    }
                    float acc = (a0 + a1) + (a2 + a3);
                    s[j] = (kt + c + j <= qg) ? acc : -1e30f;
                }
                float tmax = s[0];
                #pragma unroll
                for (int j = 1; j < 16; j++) tmax = fmaxf(tmax, s[j]);
                float mnew = fmaxf(m, tmax);
                float corr = __expf(m - mnew);
                l *= corr;
                #pragma unroll
                for (int d = 0; d < D_K; d++) o[d] *= corr;
                m = mnew;
                #pragma unroll
                for (int j = 0; j < 16; j++) {
                    float p = __expf(s[j] - mnew);
                    l += p;
                    const float4* vr = reinterpret_cast<const float4*>(&Vs[c + j][0]);
                    #pragma unroll
                    for (int d4 = 0; d4 < 16; d4++) {
                        float4 vv = vr[d4];
                        o[d4 * 4 + 0] += p * vv.x;
                        o[d4 * 4 + 1] += p * vv.y;
                        o[d4 * 4 + 2] += p * vv.z;
                        o[d4 * 4 + 3] += p * vv.w;
                    }
                }
            }
        }
        __syncthreads();
    }

    float inv = 1.f / l;
    #pragma unroll
    for (int d = 0; d < D_K; d += 4) {
        float4 out;
        out.x = o[d + 0] * inv;
        out.y = o[d + 1] * inv;
        out.z = o[d + 2] * inv;
        out.w = o[d + 3] * inv;
        *reinterpret_cast<float4*>(&Ob[(size_t)qg * D_MODEL + d]) = out;
    }
}

// ---------------------------------------------------------------------------
// Launch
// ---------------------------------------------------------------------------
extern "C" void kernel_launch(void* const* d_in, const int* in_sizes, int n_in,
                              void* d_out, int out_size)
{
    (void)in_sizes; (void)n_in; (void)out_size;
    const float* q    = (const float*)d_in[0];
    const float* k    = (const float*)d_in[1];
    const float* v    = (const float*)d_in[2];
    // d_in[3] = mask (causal tril) — analytic
    const float* wq_w = (const float*)d_in[4];
    const float* wq_b = (const float*)d_in[5];
    const float* wk_w = (const float*)d_in[6];
    const float* wk_b = (const float*)d_in[7];
    const float* wv_w = (const float*)d_in[8];
    const float* wv_b = (const float*)d_in[9];
    const float* wo_w = (const float*)d_in[10];
    const float* wo_b = (const float*)d_in[11];
    float* out = (float*)d_out;

    void *pQ, *pK, *pV, *pC;
    cudaGetSymbolAddress(&pQ, g_Q);
    cudaGetSymbolAddress(&pK, g_K);
    cudaGetSymbolAddress(&pV, g_V);
    cudaGetSymbolAddress(&pC, g_ctx);
    float* Qp = (float*)pQ;
    float* Kp = (float*)pK;
    float* Vp = (float*)pV;
    float* Cp = (float*)pC;

    dim3 gemmGrid(D_MODEL / BN, M_TOTAL / BM);   // (8, 32) = 256 CTAs
    gemm_tf32_mma<<<gemmGrid, 256>>>(q, wq_w, wq_b, Qp, M_TOTAL, D_MODEL, D_MODEL);
    gemm_tf32_mma<<<gemmGrid, 256>>>(k, wk_w, wk_b, Kp, M_TOTAL, D_MODEL, D_MODEL);
    gemm_tf32_mma<<<gemmGrid, 256>>>(v, wv_w, wv_b, Vp, M_TOTAL, D_MODEL, D_MODEL);

    dim3 attnGrid(SEQ / BQ, HEADS, BATCH);       // (16, 16, 2)
    flash_attn_causal<<<attnGrid, BQ>>>(Qp, Kp, Vp, Cp);

    gemm_tf32_mma<<<gemmGrid, 256>>>(Cp, wo_w, wo_b, out, M_TOTAL, D_MODEL, D_MODEL);
}

// round 4
// speedup vs baseline: 3.9167x; 2.5068x over previous
#include <cuda_runtime.h>
#include <cstdint>
#include <cstddef>

#define D_MODEL 1024
#define HEADS   16
#define D_K     64
#define BATCH   2
#define SEQ     2048
#define M_TOTAL (BATCH * SEQ)   // 4096

// Scratch (allocation-free rule: __device__ globals)
__device__ float g_Q[M_TOTAL * D_MODEL];
__device__ float g_K[M_TOTAL * D_MODEL];
__device__ float g_V[M_TOTAL * D_MODEL];
__device__ float g_ctx[M_TOTAL * D_MODEL];

// ---------------------------------------------------------------------------
// tf32 helpers (baseline PTX, legal on compute_103)
// ---------------------------------------------------------------------------
__device__ __forceinline__ float tf32_rna(float x) {
    uint32_t r;
    asm("cvt.rna.tf32.f32 %0, %1;" : "=r"(r) : "f"(x));
    return __uint_as_float(r);
}
__device__ __forceinline__ uint32_t tf32u(float x) {
    uint32_t r;
    asm("cvt.rna.tf32.f32 %0, %1;" : "=r"(r) : "f"(x));
    return r;
}

__device__ __forceinline__ void mma_tf32_16x8x8(
    float& d0, float& d1, float& d2, float& d3,
    uint32_t a0, uint32_t a1, uint32_t a2, uint32_t a3,
    uint32_t b0, uint32_t b1)
{
    asm volatile(
        "mma.sync.aligned.m16n8k8.row.col.f32.tf32.tf32.f32 "
        "{%0,%1,%2,%3}, {%4,%5,%6,%7}, {%8,%9}, {%0,%1,%2,%3};"
        : "+f"(d0), "+f"(d1), "+f"(d2), "+f"(d3)
        : "r"(a0), "r"(a1), "r"(a2), "r"(a3), "r"(b0), "r"(b1));
}

// ---------------------------------------------------------------------------
// tf32 mma.sync GEMM (NT + bias): C[M,N] = A[M,K] * W[N,K]^T + bias[N]
// 128x128 CTA tile, BK=32, 256 threads (8 warps, 2x4 grid), 64x32 warp tile.
// ---------------------------------------------------------------------------
#define BM  128
#define BN  128
#define BKG 32
#define PAD 4
#define LDP (BKG + PAD)

__global__ __launch_bounds__(256, 2)
void gemm_tf32_mma(const float* __restrict__ A,
                   const float* __restrict__ W,
                   const float* __restrict__ bias,
                   float* __restrict__ C,
                   int M, int N, int K)
{
    __shared__ float As[BM][LDP];
    __shared__ float Bs[BN][LDP];

    const int tid  = threadIdx.x;
    const int wid  = tid >> 5;
    const int lane = tid & 31;
    const int wm = wid & 1;
    const int wn = wid >> 1;
    const int rowBase = blockIdx.y * BM;
    const int colBase = blockIdx.x * BN;
    const int warpRow = wm * 64;
    const int warpCol = wn * 32;

    const int ldr  = tid >> 3;
    const int ldc4 = tid & 7;

    float acc[4][4][4];
    #pragma unroll
    for (int mt = 0; mt < 4; mt++)
        #pragma unroll
        for (int nt = 0; nt < 4; nt++)
            #pragma unroll
            for (int i = 0; i < 4; i++) acc[mt][nt][i] = 0.f;

    float4 pa[4], pb[4];

    #pragma unroll
    for (int i = 0; i < 4; i++) {
        int r = ldr + i * 32;
        pa[i] = *reinterpret_cast<const float4*>(&A[(size_t)(rowBase + r) * K + ldc4 * 4]);
        pb[i] = *reinterpret_cast<const float4*>(&W[(size_t)(colBase + r) * K + ldc4 * 4]);
    }
    #pragma unroll
    for (int i = 0; i < 4; i++) {
        int r = ldr + i * 32;
        float4 va = pa[i], vb = pb[i];
        As[r][ldc4*4+0] = tf32_rna(va.x); As[r][ldc4*4+1] = tf32_rna(va.y);
        As[r][ldc4*4+2] = tf32_rna(va.z); As[r][ldc4*4+3] = tf32_rna(va.w);
        Bs[r][ldc4*4+0] = tf32_rna(vb.x); Bs[r][ldc4*4+1] = tf32_rna(vb.y);
        Bs[r][ldc4*4+2] = tf32_rna(vb.z); Bs[r][ldc4*4+3] = tf32_rna(vb.w);
    }
    __syncthreads();

    for (int kt = 0; kt < K; kt += BKG) {
        if (kt + BKG < K) {
            #pragma unroll
            for (int i = 0; i < 4; i++) {
                int r = ldr + i * 32;
                pa[i] = *reinterpret_cast<const float4*>(
                    &A[(size_t)(rowBase + r) * K + kt + BKG + ldc4 * 4]);
                pb[i] = *reinterpret_cast<const float4*>(
                    &W[(size_t)(colBase + r) * K + kt + BKG + ldc4 * 4]);
            }
        }

        #pragma unroll
        for (int kk = 0; kk < BKG; kk += 8) {
            const int r0 = warpRow + (lane >> 2);
            const int n0 = warpCol + (lane >> 2);
            const int kA = kk + (lane & 3);
            uint32_t af[4][4], bf[4][2];
            #pragma unroll
            for (int mt = 0; mt < 4; mt++) {
                af[mt][0] = __float_as_uint(As[r0 + mt*16    ][kA    ]);
                af[mt][1] = __float_as_uint(As[r0 + mt*16 + 8][kA    ]);
                af[mt][2] = __float_as_uint(As[r0 + mt*16    ][kA + 4]);
                af[mt][3] = __float_as_uint(As[r0 + mt*16 + 8][kA + 4]);
            }
            #pragma unroll
            for (int nt = 0; nt < 4; nt++) {
                bf[nt][0] = __float_as_uint(Bs[n0 + nt*8][kA    ]);
                bf[nt][1] = __float_as_uint(Bs[n0 + nt*8][kA + 4]);
            }
            #pragma unroll
            for (int mt = 0; mt < 4; mt++)
                #pragma unroll
                for (int nt = 0; nt < 4; nt++)
                    mma_tf32_16x8x8(acc[mt][nt][0], acc[mt][nt][1],
                                    acc[mt][nt][2], acc[mt][nt][3],
                                    af[mt][0], af[mt][1], af[mt][2], af[mt][3],
                                    bf[nt][0], bf[nt][1]);
        }
        __syncthreads();

        if (kt + BKG < K) {
            #pragma unroll
            for (int i = 0; i < 4; i++) {
                int r = ldr + i * 32;
                float4 va = pa[i], vb = pb[i];
                As[r][ldc4*4+0] = tf32_rna(va.x); As[r][ldc4*4+1] = tf32_rna(va.y);
                As[r][ldc4*4+2] = tf32_rna(va.z); As[r][ldc4*4+3] = tf32_rna(va.w);
                Bs[r][ldc4*4+0] = tf32_rna(vb.x); Bs[r][ldc4*4+1] = tf32_rna(vb.y);
                Bs[r][ldc4*4+2] = tf32_rna(vb.z); Bs[r][ldc4*4+3] = tf32_rna(vb.w);
            }
            __syncthreads();
        }
    }

    #pragma unroll
    for (int nt = 0; nt < 4; nt++) {
        const int col = colBase + warpCol + nt * 8 + 2 * (lane & 3);
        const float b0 = bias[col], b1 = bias[col + 1];
        #pragma unroll
        for (int mt = 0; mt < 4; mt++) {
            const int row = rowBase + warpRow + mt * 16 + (lane >> 2);
            float2 v0 = make_float2(acc[mt][nt][0] + b0, acc[mt][nt][1] + b1);
            float2 v1 = make_float2(acc[mt][nt][2] + b0, acc[mt][nt][3] + b1);
            *reinterpret_cast<float2*>(&C[(size_t)row * N + col])       = v0;
            *reinterpret_cast<float2*>(&C[(size_t)(row + 8) * N + col]) = v1;
        }
    }
}

// ---------------------------------------------------------------------------
// Tensor-core causal flash attention (tf32 mma.sync).
// CTA: 128 q-rows, 256 threads (8 warps x m16 row band).
// K/V chunks of 64 keys in smem; V stored transposed for the PV mma.
// ---------------------------------------------------------------------------
#define AQ  128
#define AKV 64
#define AP  68   // smem pitch in floats (68 % 32 == 4 -> conflict-free frag reads)

__global__ __launch_bounds__(256, 1)
void flash_attn_tc(const float* __restrict__ Qg,
                   const float* __restrict__ Kg,
                   const float* __restrict__ Vg,
                   float* __restrict__ Og)
{
    __shared__ float sA[64 * AP];   // Q rows 0-63 staging, then K tile [key][d]
    __shared__ float sB[64 * AP];   // Q rows 64-127 staging, then V^T tile [d][key]

    const int tid  = threadIdx.x;
    const int w    = tid >> 5;
    const int lane = tid & 31;
    const int h = blockIdx.y, b = blockIdx.z;
    const int qbase = blockIdx.x * AQ;

    const float* Qb = Qg + (size_t)b * SEQ * D_MODEL + h * D_K;
    const float* Kb = Kg + (size_t)b * SEQ * D_MODEL + h * D_K;
    const float* Vb = Vg + (size_t)b * SEQ * D_MODEL + h * D_K;
    float*       Ob = Og + (size_t)b * SEQ * D_MODEL + h * D_K;

    // ---- stage Q (scaled by 1/sqrt(64), tf32-rounded) ----
    #pragma unroll
    for (int i = 0; i < 8; i++) {
        int idx = tid + i * 256;              // 0..2047 float4 units
        int r = idx >> 4, d4 = idx & 15;
        float4 v = *reinterpret_cast<const float4*>(
            &Qb[(size_t)(qbase + r) * D_MODEL + d4 * 4]);
        float* dst = (r < 64 ? sA : sB) + (r & 63) * AP + d4 * 4;
        dst[0] = tf32_rna(v.x * 0.125f);
        dst[1] = tf32_rna(v.y * 0.125f);
        dst[2] = tf32_rna(v.z * 0.125f);
        dst[3] = tf32_rna(v.w * 0.125f);
    }
    __syncthreads();

    // ---- extract Q A-fragments (warp band = rows w*16 .. w*16+15) ----
    uint32_t qf[8][4];
    {
        const float* qsrc = (w < 4) ? sA : sB;
        int r0 = (w * 16 + (lane >> 2)) & 63;
        int c  = lane & 3;
        #pragma unroll
        for (int kk = 0; kk < 8; kk++) {
            qf[kk][0] = __float_as_uint(qsrc[ r0      * AP + kk * 8 + c    ]);
            qf[kk][1] = __float_as_uint(qsrc[(r0 + 8) * AP + kk * 8 + c    ]);
            qf[kk][2] = __float_as_uint(qsrc[ r0      * AP + kk * 8 + c + 4]);
            qf[kk][3] = __float_as_uint(qsrc[(r0 + 8) * AP + kk * 8 + c + 4]);
        }
    }
    __syncthreads();

    float of[8][4];
    #pragma unroll
    for (int j = 0; j < 8; j++) { of[j][0]=of[j][1]=of[j][2]=of[j][3]=0.f; }
    float m0 = -1e30f, m1 = -1e30f, l0 = 0.f, l1 = 0.f;

    const int rowg0 = qbase + w * 16 + (lane >> 2);
    const int rowg1 = rowg0 + 8;
    const int warpRowMax = qbase + w * 16 + 15;
    const int nchunks = (qbase + AQ) / AKV;

    const int cbase = lane & ~3, cq = lane & 3;
    const int slo = cbase | (cq >> 1);
    const int shi = slo + 2;
    const bool odd = cq & 1;

    for (int ch = 0; ch < nchunks; ch++) {
        const int kt = ch * AKV;

        // ---- load K chunk -> sA [key][d], V chunk -> sB [d][key] (tf32) ----
        #pragma unroll
        for (int i = 0; i < 4; i++) {
            int idx = tid + i * 256;          // 0..1023 float4
            int r = idx >> 4, d4 = idx & 15;
            float4 kv = *reinterpret_cast<const float4*>(
                &Kb[(size_t)(kt + r) * D_MODEL + d4 * 4]);
            float* dk = sA + r * AP + d4 * 4;
            dk[0]=tf32_rna(kv.x); dk[1]=tf32_rna(kv.y);
            dk[2]=tf32_rna(kv.z); dk[3]=tf32_rna(kv.w);
            float4 vv = *reinterpret_cast<const float4*>(
                &Vb[(size_t)(kt + r) * D_MODEL + d4 * 4]);
            sB[(d4*4+0)*AP + r] = tf32_rna(vv.x);
            sB[(d4*4+1)*AP + r] = tf32_rna(vv.y);
            sB[(d4*4+2)*AP + r] = tf32_rna(vv.z);
            sB[(d4*4+3)*AP + r] = tf32_rna(vv.w);
        }
        __syncthreads();

        if (kt <= warpRowMax) {
            // ---- S = Q K^T ----
            float cf[8][4];
            #pragma unroll
            for (int j = 0; j < 8; j++) {
                cf[j][0]=cf[j][1]=cf[j][2]=cf[j][3]=0.f;
                const int key = j * 8 + (lane >> 2);
                #pragma unroll
                for (int kk = 0; kk < 8; kk++) {
                    uint32_t b0 = __float_as_uint(sA[key*AP + kk*8 + cq    ]);
                    uint32_t b1 = __float_as_uint(sA[key*AP + kk*8 + cq + 4]);
                    mma_tf32_16x8x8(cf[j][0], cf[j][1], cf[j][2], cf[j][3],
                                    qf[kk][0], qf[kk][1], qf[kk][2], qf[kk][3],
                                    b0, b1);
                }
            }

            // ---- causal mask (only for diagonal-band chunks) ----
            if (kt + AKV - 1 > qbase + w * 16) {
                #pragma unroll
                for (int j = 0; j < 8; j++) {
                    int col = kt + j * 8 + 2 * cq;
                    if (col     > rowg0) cf[j][0] = -1e30f;
                    if (col + 1 > rowg0) cf[j][1] = -1e30f;
                    if (col     > rowg1) cf[j][2] = -1e30f;
                    if (col + 1 > rowg1) cf[j][3] = -1e30f;
                }
            }

            // ---- online softmax ----
            float mx0 = -1e30f, mx1 = -1e30f;
            #pragma unroll
            for (int j = 0; j < 8; j++) {
                mx0 = fmaxf(mx0, fmaxf(cf[j][0], cf[j][1]));
                mx1 = fmaxf(mx1, fmaxf(cf[j][2], cf[j][3]));
            }
            mx0 = fmaxf(mx0, __shfl_xor_sync(0xFFFFFFFFu, mx0, 1));
            mx0 = fmaxf(mx0, __shfl_xor_sync(0xFFFFFFFFu, mx0, 2));
            mx1 = fmaxf(mx1, __shfl_xor_sync(0xFFFFFFFFu, mx1, 1));
            mx1 = fmaxf(mx1, __shfl_xor_sync(0xFFFFFFFFu, mx1, 2));

            const float mn0 = fmaxf(m0, mx0), mn1 = fmaxf(m1, mx1);
            const float corr0 = __expf(m0 - mn0), corr1 = __expf(m1 - mn1);
            m0 = mn0; m1 = mn1;

            float la0 = 0.f, la1 = 0.f;
            #pragma unroll
            for (int j = 0; j < 8; j++) {
                cf[j][0] = __expf(cf[j][0] - mn0);
                cf[j][1] = __expf(cf[j][1] - mn0);
                cf[j][2] = __expf(cf[j][2] - mn1);
                cf[j][3] = __expf(cf[j][3] - mn1);
                la0 += cf[j][0] + cf[j][1];
                la1 += cf[j][2] + cf[j][3];
            }
            la0 += __shfl_xor_sync(0xFFFFFFFFu, la0, 1);
            la0 += __shfl_xor_sync(0xFFFFFFFFu, la0, 2);
            la1 += __shfl_xor_sync(0xFFFFFFFFu, la1, 1);
            la1 += __shfl_xor_sync(0xFFFFFFFFu, la1, 2);
            l0 = l0 * corr0 + la0;
            l1 = l1 * corr1 + la1;

            #pragma unroll
            for (int j = 0; j < 8; j++) {
                of[j][0] *= corr0; of[j][1] *= corr0;
                of[j][2] *= corr1; of[j][3] *= corr1;
            }

            // ---- O += P V  (C-frag -> A-frag via quad shuffles) ----
            #pragma unroll
            for (int kk = 0; kk < 8; kk++) {
                uint32_t p0 = tf32u(cf[kk][0]), p1 = tf32u(cf[kk][1]);
                uint32_t p2 = tf32u(cf[kk][2]), p3 = tf32u(cf[kk][3]);
                uint32_t u0 = __shfl_sync(0xFFFFFFFFu, p0, slo);
                uint32_t u1 = __shfl_sync(0xFFFFFFFFu, p1, slo);
                uint32_t u2 = __shfl_sync(0xFFFFFFFFu, p2, slo);
                uint32_t u3 = __shfl_sync(0xFFFFFFFFu, p3, slo);
                uint32_t x0 = __shfl_sync(0xFFFFFFFFu, p0, shi);
                uint32_t x1 = __shfl_sync(0xFFFFFFFFu, p1, shi);
                uint32_t x2 = __shfl_sync(0xFFFFFFFFu, p2, shi);
                uint32_t x3 = __shfl_sync(0xFFFFFFFFu, p3, shi);
                uint32_t a0 = odd ? u1 : u0;   // P[r,   c  ]
                uint32_t a1 = odd ? u3 : u2;   // P[r+8, c  ]
                uint32_t a2 = odd ? x1 : x0;   // P[r,   c+4]
                uint32_t a3 = odd ? x3 : x2;   // P[r+8, c+4]
                #pragma unroll
                for (int j2 = 0; j2 < 8; j2++) {
                    const int d = j2 * 8 + (lane >> 2);
                    uint32_t b0 = __float_as_uint(sB[d*AP + kk*8 + cq    ]);
                    uint32_t b1 = __float_as_uint(sB[d*AP + kk*8 + cq + 4]);
                    mma_tf32_16x8x8(of[j2][0], of[j2][1], of[j2][2], of[j2][3],
                                    a0, a1, a2, a3, b0, b1);
                }
            }
        }
        __syncthreads();
    }

    // ---- normalize + write ----
    const float inv0 = 1.f / l0, inv1 = 1.f / l1;
    #pragma unroll
    for (int j2 = 0; j2 < 8; j2++) {
        int col = j2 * 8 + 2 * cq;
        float2 v0 = make_float2(of[j2][0] * inv0, of[j2][1] * inv0);
        float2 v1 = make_float2(of[j2][2] * inv1, of[j2][3] * inv1);
        *reinterpret_cast<float2*>(&Ob[(size_t)rowg0 * D_MODEL + col]) = v0;
        *reinterpret_cast<float2*>(&Ob[(size_t)rowg1 * D_MODEL + col]) = v1;
    }
}

// ---------------------------------------------------------------------------
// Launch
// ---------------------------------------------------------------------------
extern "C" void kernel_launch(void* const* d_in, const int* in_sizes, int n_in,
                              void* d_out, int out_size)
{
    (void)in_sizes; (void)n_in; (void)out_size;
    const float* q    = (const float*)d_in[0];
    const float* k    = (const float*)d_in[1];
    const float* v    = (const float*)d_in[2];
    // d_in[3] = mask (causal tril) — analytic
    const float* wq_w = (const float*)d_in[4];
    const float* wq_b = (const float*)d_in[5];
    const float* wk_w = (const float*)d_in[6];
    const float* wk_b = (const float*)d_in[7];
    const float* wv_w = (const float*)d_in[8];
    const float* wv_b = (const float*)d_in[9];
    const float* wo_w = (const float*)d_in[10];
    const float* wo_b = (const float*)d_in[11];
    float* out = (float*)d_out;

    void *pQ, *pK, *pV, *pC;
    cudaGetSymbolAddress(&pQ, g_Q);
    cudaGetSymbolAddress(&pK, g_K);
    cudaGetSymbolAddress(&pV, g_V);
    cudaGetSymbolAddress(&pC, g_ctx);
    float* Qp = (float*)pQ;
    float* Kp = (float*)pK;
    float* Vp = (float*)pV;
    float* Cp = (float*)pC;

    dim3 gemmGrid(D_MODEL / BN, M_TOTAL / BM);   // (8, 32) = 256 CTAs
    gemm_tf32_mma<<<gemmGrid, 256>>>(q, wq_w, wq_b, Qp, M_TOTAL, D_MODEL, D_MODEL);
    gemm_tf32_mma<<<gemmGrid, 256>>>(k, wk_w, wk_b, Kp, M_TOTAL, D_MODEL, D_MODEL);
    gemm_tf32_mma<<<gemmGrid, 256>>>(v, wv_w, wv_b, Vp, M_TOTAL, D_MODEL, D_MODEL);

    dim3 attnGrid(SEQ / AQ, HEADS, BATCH);       // (16, 16, 2)
    flash_attn_tc<<<attnGrid, 256>>>(Qp, Kp, Vp, Cp);

    gemm_tf32_mma<<<gemmGrid, 256>>>(Cp, wo_w, wo_b, out, M_TOTAL, D_MODEL, D_MODEL);
}

// round 5
// speedup vs baseline: 4.2314x; 1.0804x over previous
#include <cuda_runtime.h>
#include <cstdint>
#include <cstddef>

#define D_MODEL 1024
#define HEADS   16
#define D_K     64
#define BATCH   2
#define SEQ     2048
#define M_TOTAL (BATCH * SEQ)   // 4096

// Scratch (allocation-free rule: __device__ globals)
__device__ float g_Q[M_TOTAL * D_MODEL];
__device__ float g_K[M_TOTAL * D_MODEL];
__device__ float g_V[M_TOTAL * D_MODEL];
__device__ float g_ctx[M_TOTAL * D_MODEL];

// ---------------------------------------------------------------------------
// tf32 helpers (baseline PTX, legal on compute_103)
// ---------------------------------------------------------------------------
__device__ __forceinline__ float tf32_rna(float x) {
    uint32_t r;
    asm("cvt.rna.tf32.f32 %0, %1;" : "=r"(r) : "f"(x));
    return __uint_as_float(r);
}
__device__ __forceinline__ uint32_t tf32u(float x) {
    uint32_t r;
    asm("cvt.rna.tf32.f32 %0, %1;" : "=r"(r) : "f"(x));
    return r;
}

__device__ __forceinline__ void mma_tf32_16x8x8(
    float& d0, float& d1, float& d2, float& d3,
    uint32_t a0, uint32_t a1, uint32_t a2, uint32_t a3,
    uint32_t b0, uint32_t b1)
{
    asm volatile(
        "mma.sync.aligned.m16n8k8.row.col.f32.tf32.tf32.f32 "
        "{%0,%1,%2,%3}, {%4,%5,%6,%7}, {%8,%9}, {%0,%1,%2,%3};"
        : "+f"(d0), "+f"(d1), "+f"(d2), "+f"(d3)
        : "r"(a0), "r"(a1), "r"(a2), "r"(a3), "r"(b0), "r"(b1));
}

// ---------------------------------------------------------------------------
// tf32 mma.sync GEMM body (NT + bias): C[M,N] = A[M,K] * W[N,K]^T + bias[N]
// 128x128 CTA tile, BK=32, 256 threads (8 warps, 2x4 grid), 64x32 warp tile.
// ---------------------------------------------------------------------------
#define BM  128
#define BN  128
#define BKG 32
#define PAD 4
#define LDP (BKG + PAD)

__device__ __forceinline__ void gemm_body(
    const float* __restrict__ A,
    const float* __restrict__ W,
    const float* __restrict__ bias,
    float* __restrict__ C,
    int M, int N, int K)
{
    __shared__ float As[BM][LDP];
    __shared__ float Bs[BN][LDP];

    const int tid  = threadIdx.x;
    const int wid  = tid >> 5;
    const int lane = tid & 31;
    const int wm = wid & 1;
    const int wn = wid >> 1;
    const int rowBase = blockIdx.y * BM;
    const int colBase = blockIdx.x * BN;
    const int warpRow = wm * 64;
    const int warpCol = wn * 32;

    const int ldr  = tid >> 3;
    const int ldc4 = tid & 7;

    float acc[4][4][4];
    #pragma unroll
    for (int mt = 0; mt < 4; mt++)
        #pragma unroll
        for (int nt = 0; nt < 4; nt++)
            #pragma unroll
            for (int i = 0; i < 4; i++) acc[mt][nt][i] = 0.f;

    float4 pa[4], pb[4];

    #pragma unroll
    for (int i = 0; i < 4; i++) {
        int r = ldr + i * 32;
        pa[i] = *reinterpret_cast<const float4*>(&A[(size_t)(rowBase + r) * K + ldc4 * 4]);
        pb[i] = *reinterpret_cast<const float4*>(&W[(size_t)(colBase + r) * K + ldc4 * 4]);
    }
    #pragma unroll
    for (int i = 0; i < 4; i++) {
        int r = ldr + i * 32;
        float4 va = pa[i], vb = pb[i];
        As[r][ldc4*4+0] = tf32_rna(va.x); As[r][ldc4*4+1] = tf32_rna(va.y);
        As[r][ldc4*4+2] = tf32_rna(va.z); As[r][ldc4*4+3] = tf32_rna(va.w);
        Bs[r][ldc4*4+0] = tf32_rna(vb.x); Bs[r][ldc4*4+1] = tf32_rna(vb.y);
        Bs[r][ldc4*4+2] = tf32_rna(vb.z); Bs[r][ldc4*4+3] = tf32_rna(vb.w);
    }
    __syncthreads();

    for (int kt = 0; kt < K; kt += BKG) {
        if (kt + BKG < K) {
            #pragma unroll
            for (int i = 0; i < 4; i++) {
                int r = ldr + i * 32;
                pa[i] = *reinterpret_cast<const float4*>(
                    &A[(size_t)(rowBase + r) * K + kt + BKG + ldc4 * 4]);
                pb[i] = *reinterpret_cast<const float4*>(
                    &W[(size_t)(colBase + r) * K + kt + BKG + ldc4 * 4]);
            }
        }

        #pragma unroll
        for (int kk = 0; kk < BKG; kk += 8) {
            const int r0 = warpRow + (lane >> 2);
            const int n0 = warpCol + (lane >> 2);
            const int kA = kk + (lane & 3);
            uint32_t af[4][4], bf[4][2];
            #pragma unroll
            for (int mt = 0; mt < 4; mt++) {
                af[mt][0] = __float_as_uint(As[r0 + mt*16    ][kA    ]);
                af[mt][1] = __float_as_uint(As[r0 + mt*16 + 8][kA    ]);
                af[mt][2] = __float_as_uint(As[r0 + mt*16    ][kA + 4]);
                af[mt][3] = __float_as_uint(As[r0 + mt*16 + 8][kA + 4]);
            }
            #pragma unroll
            for (int nt = 0; nt < 4; nt++) {
                bf[nt][0] = __float_as_uint(Bs[n0 + nt*8][kA    ]);
                bf[nt][1] = __float_as_uint(Bs[n0 + nt*8][kA + 4]);
            }
            #pragma unroll
            for (int mt = 0; mt < 4; mt++)
                #pragma unroll
                for (int nt = 0; nt < 4; nt++)
                    mma_tf32_16x8x8(acc[mt][nt][0], acc[mt][nt][1],
                                    acc[mt][nt][2], acc[mt][nt][3],
                                    af[mt][0], af[mt][1], af[mt][2], af[mt][3],
                                    bf[nt][0], bf[nt][1]);
        }
        __syncthreads();

        if (kt + BKG < K) {
            #pragma unroll
            for (int i = 0; i < 4; i++) {
                int r = ldr + i * 32;
                float4 va = pa[i], vb = pb[i];
                As[r][ldc4*4+0] = tf32_rna(va.x); As[r][ldc4*4+1] = tf32_rna(va.y);
                As[r][ldc4*4+2] = tf32_rna(va.z); As[r][ldc4*4+3] = tf32_rna(va.w);
                Bs[r][ldc4*4+0] = tf32_rna(vb.x); Bs[r][ldc4*4+1] = tf32_rna(vb.y);
                Bs[r][ldc4*4+2] = tf32_rna(vb.z); Bs[r][ldc4*4+3] = tf32_rna(vb.w);
            }
            __syncthreads();
        }
    }

    #pragma unroll
    for (int nt = 0; nt < 4; nt++) {
        const int col = colBase + warpCol + nt * 8 + 2 * (lane & 3);
        const float b0 = bias[col], b1 = bias[col + 1];
        #pragma unroll
        for (int mt = 0; mt < 4; mt++) {
            const int row = rowBase + warpRow + mt * 16 + (lane >> 2);
            float2 v0 = make_float2(acc[mt][nt][0] + b0, acc[mt][nt][1] + b1);
            float2 v1 = make_float2(acc[mt][nt][2] + b0, acc[mt][nt][3] + b1);
            *reinterpret_cast<float2*>(&C[(size_t)row * N + col])       = v0;
            *reinterpret_cast<float2*>(&C[(size_t)(row + 8) * N + col]) = v1;
        }
    }
}

// Single GEMM (used for the output projection)
__global__ __launch_bounds__(256, 2)
void gemm_tf32_mma(const float* __restrict__ A,
                   const float* __restrict__ W,
                   const float* __restrict__ bias,
                   float* __restrict__ C,
                   int M, int N, int K)
{
    gemm_body(A, W, bias, C, M, N, K);
}

// Fused Q/K/V projections: blockIdx.z selects the operand triplet.
__global__ __launch_bounds__(256, 2)
void gemm_tf32_qkv(const float* __restrict__ qin,  const float* __restrict__ kin,
                   const float* __restrict__ vin,
                   const float* __restrict__ wq,   const float* __restrict__ wk,
                   const float* __restrict__ wv,
                   const float* __restrict__ bq,   const float* __restrict__ bk,
                   const float* __restrict__ bv,
                   float* __restrict__ Qo, float* __restrict__ Ko, float* __restrict__ Vo)
{
    const float *A, *W, *bias;
    float* C;
    if (blockIdx.z == 0)      { A = qin; W = wq; bias = bq; C = Qo; }
    else if (blockIdx.z == 1) { A = kin; W = wk; bias = bk; C = Ko; }
    else                      { A = vin; W = wv; bias = bv; C = Vo; }
    gemm_body(A, W, bias, C, M_TOTAL, D_MODEL, D_MODEL);
}

// ---------------------------------------------------------------------------
// Tensor-core causal flash attention (tf32 mma.sync), software-pipelined K/V.
// CTA: 128 q-rows, 256 threads (8 warps x m16 row band).
// Heaviest q-blocks scheduled first (reverse blockIdx.x mapping).
// ---------------------------------------------------------------------------
#define AQ  128
#define AKV 64
#define AP  68   // smem pitch in floats (68 % 32 == 4 -> conflict-free frag reads)

__global__ __launch_bounds__(256, 1)
void flash_attn_tc(const float* __restrict__ Qg,
                   const float* __restrict__ Kg,
                   const float* __restrict__ Vg,
                   float* __restrict__ Og)
{
    __shared__ float sA[64 * AP];   // Q rows 0-63 staging, then K tile [key][d]
    __shared__ float sB[64 * AP];   // Q rows 64-127 staging, then V^T tile [d][key]

    const int tid  = threadIdx.x;
    const int w    = tid >> 5;
    const int lane = tid & 31;
    const int h = blockIdx.y, b = blockIdx.z;
    // heaviest-first: reverse the q-block order so the diagonal-heavy CTAs land in wave 1
    const int qblk = (int)gridDim.x - 1 - (int)blockIdx.x;
    const int qbase = qblk * AQ;

    const float* Qb = Qg + (size_t)b * SEQ * D_MODEL + h * D_K;
    const float* Kb = Kg + (size_t)b * SEQ * D_MODEL + h * D_K;
    const float* Vb = Vg + (size_t)b * SEQ * D_MODEL + h * D_K;
    float*       Ob = Og + (size_t)b * SEQ * D_MODEL + h * D_K;

    // ---- stage Q (scaled by 1/sqrt(64), tf32-rounded) ----
    #pragma unroll
    for (int i = 0; i < 8; i++) {
        int idx = tid + i * 256;
        int r = idx >> 4, d4 = idx & 15;
        float4 v = *reinterpret_cast<const float4*>(
            &Qb[(size_t)(qbase + r) * D_MODEL + d4 * 4]);
        float* dst = (r < 64 ? sA : sB) + (r & 63) * AP + d4 * 4;
        dst[0] = tf32_rna(v.x * 0.125f);
        dst[1] = tf32_rna(v.y * 0.125f);
        dst[2] = tf32_rna(v.z * 0.125f);
        dst[3] = tf32_rna(v.w * 0.125f);
    }
    __syncthreads();

    // ---- extract Q A-fragments (warp band = rows w*16 .. w*16+15) ----
    uint32_t qf[8][4];
    {
        const float* qsrc = (w < 4) ? sA : sB;
        int r0 = (w * 16 + (lane >> 2)) & 63;
        int c  = lane & 3;
        #pragma unroll
        for (int kk = 0; kk < 8; kk++) {
            qf[kk][0] = __float_as_uint(qsrc[ r0      * AP + kk * 8 + c    ]);
            qf[kk][1] = __float_as_uint(qsrc[(r0 + 8) * AP + kk * 8 + c    ]);
            qf[kk][2] = __float_as_uint(qsrc[ r0      * AP + kk * 8 + c + 4]);
            qf[kk][3] = __float_as_uint(qsrc[(r0 + 8) * AP + kk * 8 + c + 4]);
        }
    }
    __syncthreads();

    float of[8][4];
    #pragma unroll
    for (int j = 0; j < 8; j++) { of[j][0]=of[j][1]=of[j][2]=of[j][3]=0.f; }
    float m0 = -1e30f, m1 = -1e30f, l0 = 0.f, l1 = 0.f;

    const int rowg0 = qbase + w * 16 + (lane >> 2);
    const int rowg1 = rowg0 + 8;
    const int warpRowMax = qbase + w * 16 + 15;
    const int nchunks = (qbase + AQ) / AKV;

    const int cbase = lane & ~3, cq = lane & 3;
    const int slo = cbase | (cq >> 1);
    const int shi = slo + 2;
    const bool odd = cq & 1;

    // ---- fill chunk 0 into smem ----
    #pragma unroll
    for (int i = 0; i < 4; i++) {
        int idx = tid + i * 256;
        int r = idx >> 4, d4 = idx & 15;
        float4 kv = *reinterpret_cast<const float4*>(&Kb[(size_t)r * D_MODEL + d4 * 4]);
        float* dk = sA + r * AP + d4 * 4;
        dk[0]=tf32_rna(kv.x); dk[1]=tf32_rna(kv.y);
        dk[2]=tf32_rna(kv.z); dk[3]=tf32_rna(kv.w);
        float4 vv = *reinterpret_cast<const float4*>(&Vb[(size_t)r * D_MODEL + d4 * 4]);
        sB[(d4*4+0)*AP + r] = tf32_rna(vv.x);
        sB[(d4*4+1)*AP + r] = tf32_rna(vv.y);
        sB[(d4*4+2)*AP + r] = tf32_rna(vv.z);
        sB[(d4*4+3)*AP + r] = tf32_rna(vv.w);
    }
    __syncthreads();

    for (int ch = 0; ch < nchunks; ch++) {
        const int kt = ch * AKV;
        const bool hasNext = (ch + 1 < nchunks);

        // ---- prefetch next chunk into registers (hides global latency) ----
        float4 pk[4], pv[4];
        if (hasNext) {
            const int ktn = kt + AKV;
            #pragma unroll
            for (int i = 0; i < 4; i++) {
                int idx = tid + i * 256;
                int r = idx >> 4, d4 = idx & 15;
                pk[i] = *reinterpret_cast<const float4*>(
                    &Kb[(size_t)(ktn + r) * D_MODEL + d4 * 4]);
                pv[i] = *reinterpret_cast<const float4*>(
                    &Vb[(size_t)(ktn + r) * D_MODEL + d4 * 4]);
            }
        }

        if (kt <= warpRowMax) {
            // ---- S = Q K^T ----
            float cf[8][4];
            #pragma unroll
            for (int j = 0; j < 8; j++) {
                cf[j][0]=cf[j][1]=cf[j][2]=cf[j][3]=0.f;
                const int key = j * 8 + (lane >> 2);
                #pragma unroll
                for (int kk = 0; kk < 8; kk++) {
                    uint32_t b0 = __float_as_uint(sA[key*AP + kk*8 + cq    ]);
                    uint32_t b1 = __float_as_uint(sA[key*AP + kk*8 + cq + 4]);
                    mma_tf32_16x8x8(cf[j][0], cf[j][1], cf[j][2], cf[j][3],
                                    qf[kk][0], qf[kk][1], qf[kk][2], qf[kk][3],
                                    b0, b1);
                }
            }

            // ---- causal mask (diagonal-band chunks only) ----
            if (kt + AKV - 1 > qbase + w * 16) {
                #pragma unroll
                for (int j = 0; j < 8; j++) {
                    int col = kt + j * 8 + 2 * cq;
                    if (col     > rowg0) cf[j][0] = -1e30f;
                    if (col + 1 > rowg0) cf[j][1] = -1e30f;
                    if (col     > rowg1) cf[j][2] = -1e30f;
                    if (col + 1 > rowg1) cf[j][3] = -1e30f;
                }
            }

            // ---- online softmax ----
            float mx0 = -1e30f, mx1 = -1e30f;
            #pragma unroll
            for (int j = 0; j < 8; j++) {
                mx0 = fmaxf(mx0, fmaxf(cf[j][0], cf[j][1]));
                mx1 = fmaxf(mx1, fmaxf(cf[j][2], cf[j][3]));
            }
            mx0 = fmaxf(mx0, __shfl_xor_sync(0xFFFFFFFFu, mx0, 1));
            mx0 = fmaxf(mx0, __shfl_xor_sync(0xFFFFFFFFu, mx0, 2));
            mx1 = fmaxf(mx1, __shfl_xor_sync(0xFFFFFFFFu, mx1, 1));
            mx1 = fmaxf(mx1, __shfl_xor_sync(0xFFFFFFFFu, mx1, 2));

            const float mn0 = fmaxf(m0, mx0), mn1 = fmaxf(m1, mx1);
            const float corr0 = __expf(m0 - mn0), corr1 = __expf(m1 - mn1);
            m0 = mn0; m1 = mn1;

            float la0 = 0.f, la1 = 0.f;
            #pragma unroll
            for (int j = 0; j < 8; j++) {
                cf[j][0] = __expf(cf[j][0] - mn0);
                cf[j][1] = __expf(cf[j][1] - mn0);
                cf[j][2] = __expf(cf[j][2] - mn1);
                cf[j][3] = __expf(cf[j][3] - mn1);
                la0 += cf[j][0] + cf[j][1];
                la1 += cf[j][2] + cf[j][3];
            }
            la0 += __shfl_xor_sync(0xFFFFFFFFu, la0, 1);
            la0 += __shfl_xor_sync(0xFFFFFFFFu, la0, 2);
            la1 += __shfl_xor_sync(0xFFFFFFFFu, la1, 1);
            la1 += __shfl_xor_sync(0xFFFFFFFFu, la1, 2);
            l0 = l0 * corr0 + la0;
            l1 = l1 * corr1 + la1;

            #pragma unroll
            for (int j = 0; j < 8; j++) {
                of[j][0] *= corr0; of[j][1] *= corr0;
                of[j][2] *= corr1; of[j][3] *= corr1;
            }

            // ---- O += P V  (C-frag -> A-frag via quad shuffles) ----
            #pragma unroll
            for (int kk = 0; kk < 8; kk++) {
                uint32_t p0 = tf32u(cf[kk][0]), p1 = tf32u(cf[kk][1]);
                uint32_t p2 = tf32u(cf[kk][2]), p3 = tf32u(cf[kk][3]);
                uint32_t u0 = __shfl_sync(0xFFFFFFFFu, p0, slo);
                uint32_t u1 = __shfl_sync(0xFFFFFFFFu, p1, slo);
                uint32_t u2 = __shfl_sync(0xFFFFFFFFu, p2, slo);
                uint32_t u3 = __shfl_sync(0xFFFFFFFFu, p3, slo);
                uint32_t x0 = __shfl_sync(0xFFFFFFFFu, p0, shi);
                uint32_t x1 = __shfl_sync(0xFFFFFFFFu, p1, shi);
                uint32_t x2 = __shfl_sync(0xFFFFFFFFu, p2, shi);
                uint32_t x3 = __shfl_sync(0xFFFFFFFFu, p3, shi);
                uint32_t a0 = odd ? u1 : u0;
                uint32_t a1 = odd ? u3 : u2;
                uint32_t a2 = odd ? x1 : x0;
                uint32_t a3 = odd ? x3 : x2;
                #pragma unroll
                for (int j2 = 0; j2 < 8; j2++) {
                    const int d = j2 * 8 + (lane >> 2);
                    uint32_t b0 = __float_as_uint(sB[d*AP + kk*8 + cq    ]);
                    uint32_t b1 = __float_as_uint(sB[d*AP + kk*8 + cq + 4]);
                    mma_tf32_16x8x8(of[j2][0], of[j2][1], of[j2][2], of[j2][3],
                                    a0, a1, a2, a3, b0, b1);
                }
            }
        }
        __syncthreads();   // all warps done reading this chunk's smem

        if (hasNext) {
            // ---- commit prefetched chunk to smem ----
            #pragma unroll
            for (int i = 0; i < 4; i++) {
                int idx = tid + i * 256;
                int r = idx >> 4, d4 = idx & 15;
                float* dk = sA + r * AP + d4 * 4;
                dk[0]=tf32_rna(pk[i].x); dk[1]=tf32_rna(pk[i].y);
                dk[2]=tf32_rna(pk[i].z); dk[3]=tf32_rna(pk[i].w);
                sB[(d4*4+0)*AP + r] = tf32_rna(pv[i].x);
                sB[(d4*4+1)*AP + r] = tf32_rna(pv[i].y);
                sB[(d4*4+2)*AP + r] = tf32_rna(pv[i].z);
                sB[(d4*4+3)*AP + r] = tf32_rna(pv[i].w);
            }
            __syncthreads();
        }
    }

    // ---- normalize + write ----
    const float inv0 = 1.f / l0, inv1 = 1.f / l1;
    #pragma unroll
    for (int j2 = 0; j2 < 8; j2++) {
        int col = j2 * 8 + 2 * cq;
        float2 v0 = make_float2(of[j2][0] * inv0, of[j2][1] * inv0);
        float2 v1 = make_float2(of[j2][2] * inv1, of[j2][3] * inv1);
        *reinterpret_cast<float2*>(&Ob[(size_t)rowg0 * D_MODEL + col]) = v0;
        *reinterpret_cast<float2*>(&Ob[(size_t)rowg1 * D_MODEL + col]) = v1;
    }
}

// ---------------------------------------------------------------------------
// Launch
// ---------------------------------------------------------------------------
extern "C" void kernel_launch(void* const* d_in, const int* in_sizes, int n_in,
                              void* d_out, int out_size)
{
    (void)in_sizes; (void)n_in; (void)out_size;
    const float* q    = (const float*)d_in[0];
    const float* k    = (const float*)d_in[1];
    const float* v    = (const float*)d_in[2];
    // d_in[3] = mask (causal tril) — analytic
    const float* wq_w = (const float*)d_in[4];
    const float* wq_b = (const float*)d_in[5];
    const float* wk_w = (const float*)d_in[6];
    const float* wk_b = (const float*)d_in[7];
    const float* wv_w = (const float*)d_in[8];
    const float* wv_b = (const float*)d_in[9];
    const float* wo_w = (const float*)d_in[10];
    const float* wo_b = (const float*)d_in[11];
    float* out = (float*)d_out;

    void *pQ, *pK, *pV, *pC;
    cudaGetSymbolAddress(&pQ, g_Q);
    cudaGetSymbolAddress(&pK, g_K);
    cudaGetSymbolAddress(&pV, g_V);
    cudaGetSymbolAddress(&pC, g_ctx);
    float* Qp = (float*)pQ;
    float* Kp = (float*)pK;
    float* Vp = (float*)pV;
    float* Cp = (float*)pC;

    dim3 qkvGrid(D_MODEL / BN, M_TOTAL / BM, 3);   // (8, 32, 3) = 768 CTAs
    gemm_tf32_qkv<<<qkvGrid, 256>>>(q, k, v, wq_w, wk_w, wv_w,
                                    wq_b, wk_b, wv_b, Qp, Kp, Vp);

    dim3 attnGrid(SEQ / AQ, HEADS, BATCH);         // (16, 16, 2)
    flash_attn_tc<<<attnGrid, 256>>>(Qp, Kp, Vp, Cp);

    dim3 gemmGrid(D_MODEL / BN, M_TOTAL / BM);     // (8, 32)
    gemm_tf32_mma<<<gemmGrid, 256>>>(Cp, wo_w, wo_b, out, M_TOTAL, D_MODEL, D_MODEL);
}

// round 6
// speedup vs baseline: 4.2598x; 1.0067x over previous
#include <cuda_runtime.h>
#include <cstdint>
#include <cstddef>

#define D_MODEL 1024
#define HEADS   16
#define D_K     64
#define BATCH   2
#define SEQ     2048
#define M_TOTAL (BATCH * SEQ)   // 4096

// Scratch (allocation-free rule: __device__ globals)
__device__ float g_Q[M_TOTAL * D_MODEL];
__device__ float g_K[M_TOTAL * D_MODEL];
__device__ float g_V[M_TOTAL * D_MODEL];
__device__ float g_ctx[M_TOTAL * D_MODEL];

// ---------------------------------------------------------------------------
// tf32 helpers (baseline PTX, legal on compute_103)
// ---------------------------------------------------------------------------
__device__ __forceinline__ float tf32_rna(float x) {
    uint32_t r;
    asm("cvt.rna.tf32.f32 %0, %1;" : "=r"(r) : "f"(x));
    return __uint_as_float(r);
}
__device__ __forceinline__ uint32_t tf32u(float x) {
    uint32_t r;
    asm("cvt.rna.tf32.f32 %0, %1;" : "=r"(r) : "f"(x));
    return r;
}

__device__ __forceinline__ void mma_tf32_16x8x8(
    float& d0, float& d1, float& d2, float& d3,
    uint32_t a0, uint32_t a1, uint32_t a2, uint32_t a3,
    uint32_t b0, uint32_t b1)
{
    asm volatile(
        "mma.sync.aligned.m16n8k8.row.col.f32.tf32.tf32.f32 "
        "{%0,%1,%2,%3}, {%4,%5,%6,%7}, {%8,%9}, {%0,%1,%2,%3};"
        : "+f"(d0), "+f"(d1), "+f"(d2), "+f"(d3)
        : "r"(a0), "r"(a1), "r"(a2), "r"(a3), "r"(b0), "r"(b1));
}

// ---------------------------------------------------------------------------
// tf32 mma.sync GEMM body (NT + bias): C[M,N] = A[M,K] * W[N,K]^T + bias[N]
// 128x128 CTA tile, BK=32, 256 threads (8 warps, 2x4), 64x32 warp tile.
// Double-buffered dynamic smem: ONE __syncthreads per k-tile.
// ---------------------------------------------------------------------------
#define BM  128
#define BN  128
#define BKG 32
#define PAD 4
#define LDP (BKG + PAD)
#define TILE_FLOATS (BM * LDP)                       // 4608
#define GEMM_SMEM_BYTES (4 * TILE_FLOATS * 4)        // A0,B0,A1,B1 = 73728 B

__device__ __forceinline__ void stage_store(
    float* __restrict__ As, float* __restrict__ Bs,
    const float4* pa, const float4* pb, int ldr, int ldc4)
{
    #pragma unroll
    for (int i = 0; i < 4; i++) {
        int r = ldr + i * 32;
        float4 va = pa[i], vb = pb[i];
        float* a = As + r * LDP + ldc4 * 4;
        a[0] = tf32_rna(va.x); a[1] = tf32_rna(va.y);
        a[2] = tf32_rna(va.z); a[3] = tf32_rna(va.w);
        float* bb = Bs + r * LDP + ldc4 * 4;
        bb[0] = tf32_rna(vb.x); bb[1] = tf32_rna(vb.y);
        bb[2] = tf32_rna(vb.z); bb[3] = tf32_rna(vb.w);
    }
}

__device__ __forceinline__ void gemm_body(
    const float* __restrict__ A,
    const float* __restrict__ W,
    const float* __restrict__ bias,
    float* __restrict__ C,
    int M, int N, int K)
{
    extern __shared__ float smp[];
    float* As0 = smp;
    float* Bs0 = smp + TILE_FLOATS;
    float* As1 = smp + 2 * TILE_FLOATS;
    float* Bs1 = smp + 3 * TILE_FLOATS;

    const int tid  = threadIdx.x;
    const int wid  = tid >> 5;
    const int lane = tid & 31;
    const int wm = wid & 1;
    const int wn = wid >> 1;
    const int rowBase = blockIdx.y * BM;
    const int colBase = blockIdx.x * BN;
    const int warpRow = wm * 64;
    const int warpCol = wn * 32;

    const int ldr  = tid >> 3;
    const int ldc4 = tid & 7;

    float acc[4][4][4];
    #pragma unroll
    for (int mt = 0; mt < 4; mt++)
        #pragma unroll
        for (int nt = 0; nt < 4; nt++)
            #pragma unroll
            for (int i = 0; i < 4; i++) acc[mt][nt][i] = 0.f;

    float4 pa[4], pb[4];

    // prologue: tile 0 -> regs -> buf0
    #pragma unroll
    for (int i = 0; i < 4; i++) {
        int r = ldr + i * 32;
        pa[i] = *reinterpret_cast<const float4*>(&A[(size_t)(rowBase + r) * K + ldc4 * 4]);
        pb[i] = *reinterpret_cast<const float4*>(&W[(size_t)(colBase + r) * K + ldc4 * 4]);
    }
    stage_store(As0, Bs0, pa, pb, ldr, ldc4);
    __syncthreads();

    const int NT = K / BKG;
    for (int t = 0; t < NT; t++) {
        const float* Ac = (t & 1) ? As1 : As0;
        const float* Bc = (t & 1) ? Bs1 : Bs0;
        const bool more = (t + 1 < NT);

        if (more) {
            const int ktn = (t + 1) * BKG;
            #pragma unroll
            for (int i = 0; i < 4; i++) {
                int r = ldr + i * 32;
                pa[i] = *reinterpret_cast<const float4*>(
                    &A[(size_t)(rowBase + r) * K + ktn + ldc4 * 4]);
                pb[i] = *reinterpret_cast<const float4*>(
                    &W[(size_t)(colBase + r) * K + ktn + ldc4 * 4]);
            }
        }

        #pragma unroll
        for (int kk = 0; kk < BKG; kk += 8) {
            const int r0 = warpRow + (lane >> 2);
            const int n0 = warpCol + (lane >> 2);
            const int kA = kk + (lane & 3);
            uint32_t af[4][4], bf[4][2];
            #pragma unroll
            for (int mt = 0; mt < 4; mt++) {
                af[mt][0] = __float_as_uint(Ac[(r0 + mt*16    ) * LDP + kA    ]);
                af[mt][1] = __float_as_uint(Ac[(r0 + mt*16 + 8) * LDP + kA    ]);
                af[mt][2] = __float_as_uint(Ac[(r0 + mt*16    ) * LDP + kA + 4]);
                af[mt][3] = __float_as_uint(Ac[(r0 + mt*16 + 8) * LDP + kA + 4]);
            }
            #pragma unroll
            for (int nt = 0; nt < 4; nt++) {
                bf[nt][0] = __float_as_uint(Bc[(n0 + nt*8) * LDP + kA    ]);
                bf[nt][1] = __float_as_uint(Bc[(n0 + nt*8) * LDP + kA + 4]);
            }
            #pragma unroll
            for (int mt = 0; mt < 4; mt++)
                #pragma unroll
                for (int nt = 0; nt < 4; nt++)
                    mma_tf32_16x8x8(acc[mt][nt][0], acc[mt][nt][1],
                                    acc[mt][nt][2], acc[mt][nt][3],
                                    af[mt][0], af[mt][1], af[mt][2], af[mt][3],
                                    bf[nt][0], bf[nt][1]);
        }

        if (more) {
            float* An = (t & 1) ? As0 : As1;
            float* Bn = (t & 1) ? Bs0 : Bs1;
            stage_store(An, Bn, pa, pb, ldr, ldc4);
            __syncthreads();
        }
    }

    #pragma unroll
    for (int nt = 0; nt < 4; nt++) {
        const int col = colBase + warpCol + nt * 8 + 2 * (lane & 3);
        const float b0 = bias[col], b1 = bias[col + 1];
        #pragma unroll
        for (int mt = 0; mt < 4; mt++) {
            const int row = rowBase + warpRow + mt * 16 + (lane >> 2);
            float2 v0 = make_float2(acc[mt][nt][0] + b0, acc[mt][nt][1] + b1);
            float2 v1 = make_float2(acc[mt][nt][2] + b0, acc[mt][nt][3] + b1);
            *reinterpret_cast<float2*>(&C[(size_t)row * N + col])       = v0;
            *reinterpret_cast<float2*>(&C[(size_t)(row + 8) * N + col]) = v1;
        }
    }
}

// Single GEMM (output projection)
__global__ __launch_bounds__(256, 2)
void gemm_tf32_mma(const float* __restrict__ A,
                   const float* __restrict__ W,
                   const float* __restrict__ bias,
                   float* __restrict__ C,
                   int M, int N, int K)
{
    gemm_body(A, W, bias, C, M, N, K);
}

// Fused Q/K/V projections: blockIdx.z selects the operand triplet.
__global__ __launch_bounds__(256, 2)
void gemm_tf32_qkv(const float* __restrict__ qin,  const float* __restrict__ kin,
                   const float* __restrict__ vin,
                   const float* __restrict__ wq,   const float* __restrict__ wk,
                   const float* __restrict__ wv,
                   const float* __restrict__ bq,   const float* __restrict__ bk,
                   const float* __restrict__ bv,
                   float* __restrict__ Qo, float* __restrict__ Ko, float* __restrict__ Vo)
{
    const float *A, *W, *bias;
    float* C;
    if (blockIdx.z == 0)      { A = qin; W = wq; bias = bq; C = Qo; }
    else if (blockIdx.z == 1) { A = kin; W = wk; bias = bk; C = Ko; }
    else                      { A = vin; W = wv; bias = bv; C = Vo; }
    gemm_body(A, W, bias, C, M_TOTAL, D_MODEL, D_MODEL);
}

// ---------------------------------------------------------------------------
// Tensor-core causal flash attention (tf32 mma.sync), software-pipelined K/V.
// CTA: 128 q-rows, 256 threads (8 warps x m16 row band).
// Heaviest q-blocks scheduled first (reverse blockIdx.x mapping).
// ---------------------------------------------------------------------------
#define AQ  128
#define AKV 64
#define AP  68   // smem pitch in floats (68 % 32 == 4 -> conflict-free frag reads)

__global__ __launch_bounds__(256, 1)
void flash_attn_tc(const float* __restrict__ Qg,
                   const float* __restrict__ Kg,
                   const float* __restrict__ Vg,
                   float* __restrict__ Og)
{
    __shared__ float sA[64 * AP];   // Q rows 0-63 staging, then K tile [key][d]
    __shared__ float sB[64 * AP];   // Q rows 64-127 staging, then V^T tile [d][key]

    const int tid  = threadIdx.x;
    const int w    = tid >> 5;
    const int lane = tid & 31;
    const int h = blockIdx.y, b = blockIdx.z;
    const int qblk = (int)gridDim.x - 1 - (int)blockIdx.x;
    const int qbase = qblk * AQ;

    const float* Qb = Qg + (size_t)b * SEQ * D_MODEL + h * D_K;
    const float* Kb = Kg + (size_t)b * SEQ * D_MODEL + h * D_K;
    const float* Vb = Vg + (size_t)b * SEQ * D_MODEL + h * D_K;
    float*       Ob = Og + (size_t)b * SEQ * D_MODEL + h * D_K;

    // ---- stage Q (scaled by 1/sqrt(64), tf32-rounded) ----
    #pragma unroll
    for (int i = 0; i < 8; i++) {
        int idx = tid + i * 256;
        int r = idx >> 4, d4 = idx & 15;
        float4 v = *reinterpret_cast<const float4*>(
            &Qb[(size_t)(qbase + r) * D_MODEL + d4 * 4]);
        float* dst = (r < 64 ? sA : sB) + (r & 63) * AP + d4 * 4;
        dst[0] = tf32_rna(v.x * 0.125f);
        dst[1] = tf32_rna(v.y * 0.125f);
        dst[2] = tf32_rna(v.z * 0.125f);
        dst[3] = tf32_rna(v.w * 0.125f);
    }
    __syncthreads();

    // ---- extract Q A-fragments ----
    uint32_t qf[8][4];
    {
        const float* qsrc = (w < 4) ? sA : sB;
        int r0 = (w * 16 + (lane >> 2)) & 63;
        int c  = lane & 3;
        #pragma unroll
        for (int kk = 0; kk < 8; kk++) {
            qf[kk][0] = __float_as_uint(qsrc[ r0      * AP + kk * 8 + c    ]);
            qf[kk][1] = __float_as_uint(qsrc[(r0 + 8) * AP + kk * 8 + c    ]);
            qf[kk][2] = __float_as_uint(qsrc[ r0      * AP + kk * 8 + c + 4]);
            qf[kk][3] = __float_as_uint(qsrc[(r0 + 8) * AP + kk * 8 + c + 4]);
        }
    }
    __syncthreads();

    float of[8][4];
    #pragma unroll
    for (int j = 0; j < 8; j++) { of[j][0]=of[j][1]=of[j][2]=of[j][3]=0.f; }
    float m0 = -1e30f, m1 = -1e30f, l0 = 0.f, l1 = 0.f;

    const int rowg0 = qbase + w * 16 + (lane >> 2);
    const int rowg1 = rowg0 + 8;
    const int warpRowMax = qbase + w * 16 + 15;
    const int nchunks = (qbase + AQ) / AKV;

    const int cbase = lane & ~3, cq = lane & 3;
    const int slo = cbase | (cq >> 1);
    const int shi = slo + 2;
    const bool odd = cq & 1;

    // ---- fill chunk 0 ----
    #pragma unroll
    for (int i = 0; i < 4; i++) {
        int idx = tid + i * 256;
        int r = idx >> 4, d4 = idx & 15;
        float4 kv = *reinterpret_cast<const float4*>(&Kb[(size_t)r * D_MODEL + d4 * 4]);
        float* dk = sA + r * AP + d4 * 4;
        dk[0]=tf32_rna(kv.x); dk[1]=tf32_rna(kv.y);
        dk[2]=tf32_rna(kv.z); dk[3]=tf32_rna(kv.w);
        float4 vv = *reinterpret_cast<const float4*>(&Vb[(size_t)r * D_MODEL + d4 * 4]);
        sB[(d4*4+0)*AP + r] = tf32_rna(vv.x);
        sB[(d4*4+1)*AP + r] = tf32_rna(vv.y);
        sB[(d4*4+2)*AP + r] = tf32_rna(vv.z);
        sB[(d4*4+3)*AP + r] = tf32_rna(vv.w);
    }
    __syncthreads();

    for (int ch = 0; ch < nchunks; ch++) {
        const int kt = ch * AKV;
        const bool hasNext = (ch + 1 < nchunks);

        float4 pk[4], pv[4];
        if (hasNext) {
            const int ktn = kt + AKV;
            #pragma unroll
            for (int i = 0; i < 4; i++) {
                int idx = tid + i * 256;
                int r = idx >> 4, d4 = idx & 15;
                pk[i] = *reinterpret_cast<const float4*>(
                    &Kb[(size_t)(ktn + r) * D_MODEL + d4 * 4]);
                pv[i] = *reinterpret_cast<const float4*>(
                    &Vb[(size_t)(ktn + r) * D_MODEL + d4 * 4]);
            }
        }

        if (kt <= warpRowMax) {
            // ---- S = Q K^T ----
            float cf[8][4];
            #pragma unroll
            for (int j = 0; j < 8; j++) {
                cf[j][0]=cf[j][1]=cf[j][2]=cf[j][3]=0.f;
                const int key = j * 8 + (lane >> 2);
                #pragma unroll
                for (int kk = 0; kk < 8; kk++) {
                    uint32_t b0 = __float_as_uint(sA[key*AP + kk*8 + cq    ]);
                    uint32_t b1 = __float_as_uint(sA[key*AP + kk*8 + cq + 4]);
                    mma_tf32_16x8x8(cf[j][0], cf[j][1], cf[j][2], cf[j][3],
                                    qf[kk][0], qf[kk][1], qf[kk][2], qf[kk][3],
                                    b0, b1);
                }
            }

            if (kt + AKV - 1 > qbase + w * 16) {
                #pragma unroll
                for (int j = 0; j < 8; j++) {
                    int col = kt + j * 8 + 2 * cq;
                    if (col     > rowg0) cf[j][0] = -1e30f;
                    if (col + 1 > rowg0) cf[j][1] = -1e30f;
                    if (col     > rowg1) cf[j][2] = -1e30f;
                    if (col + 1 > rowg1) cf[j][3] = -1e30f;
                }
            }

            float mx0 = -1e30f, mx1 = -1e30f;
            #pragma unroll
            for (int j = 0; j < 8; j++) {
                mx0 = fmaxf(mx0, fmaxf(cf[j][0], cf[j][1]));
                mx1 = fmaxf(mx1, fmaxf(cf[j][2], cf[j][3]));
            }
            mx0 = fmaxf(mx0, __shfl_xor_sync(0xFFFFFFFFu, mx0, 1));
            mx0 = fmaxf(mx0, __shfl_xor_sync(0xFFFFFFFFu, mx0, 2));
            mx1 = fmaxf(mx1, __shfl_xor_sync(0xFFFFFFFFu, mx1, 1));
            mx1 = fmaxf(mx1, __shfl_xor_sync(0xFFFFFFFFu, mx1, 2));

            const float mn0 = fmaxf(m0, mx0), mn1 = fmaxf(m1, mx1);
            const float corr0 = __expf(m0 - mn0), corr1 = __expf(m1 - mn1);
            m0 = mn0; m1 = mn1;

            float la0 = 0.f, la1 = 0.f;
            #pragma unroll
            for (int j = 0; j < 8; j++) {
                cf[j][0] = __expf(cf[j][0] - mn0);
                cf[j][1] = __expf(cf[j][1] - mn0);
                cf[j][2] = __expf(cf[j][2] - mn1);
                cf[j][3] = __expf(cf[j][3] - mn1);
                la0 += cf[j][0] + cf[j][1];
                la1 += cf[j][2] + cf[j][3];
            }
            la0 += __shfl_xor_sync(0xFFFFFFFFu, la0, 1);
            la0 += __shfl_xor_sync(0xFFFFFFFFu, la0, 2);
            la1 += __shfl_xor_sync(0xFFFFFFFFu, la1, 1);
            la1 += __shfl_xor_sync(0xFFFFFFFFu, la1, 2);
            l0 = l0 * corr0 + la0;
            l1 = l1 * corr1 + la1;

            #pragma unroll
            for (int j = 0; j < 8; j++) {
                of[j][0] *= corr0; of[j][1] *= corr0;
                of[j][2] *= corr1; of[j][3] *= corr1;
            }

            #pragma unroll
            for (int kk = 0; kk < 8; kk++) {
                uint32_t p0 = tf32u(cf[kk][0]), p1 = tf32u(cf[kk][1]);
                uint32_t p2 = tf32u(cf[kk][2]), p3 = tf32u(cf[kk][3]);
                uint32_t u0 = __shfl_sync(0xFFFFFFFFu, p0, slo);
                uint32_t u1 = __shfl_sync(0xFFFFFFFFu, p1, slo);
                uint32_t u2 = __shfl_sync(0xFFFFFFFFu, p2, slo);
                uint32_t u3 = __shfl_sync(0xFFFFFFFFu, p3, slo);
                uint32_t x0 = __shfl_sync(0xFFFFFFFFu, p0, shi);
                uint32_t x1 = __shfl_sync(0xFFFFFFFFu, p1, shi);
                uint32_t x2 = __shfl_sync(0xFFFFFFFFu, p2, shi);
                uint32_t x3 = __shfl_sync(0xFFFFFFFFu, p3, shi);
                uint32_t a0 = odd ? u1 : u0;
                uint32_t a1 = odd ? u3 : u2;
                uint32_t a2 = odd ? x1 : x0;
                uint32_t a3 = odd ? x3 : x2;
                #pragma unroll
                for (int j2 = 0; j2 < 8; j2++) {
                    const int d = j2 * 8 + (lane >> 2);
                    uint32_t b0 = __float_as_uint(sB[d*AP + kk*8 + cq    ]);
                    uint32_t b1 = __float_as_uint(sB[d*AP + kk*8 + cq + 4]);
                    mma_tf32_16x8x8(of[j2][0], of[j2][1], of[j2][2], of[j2][3],
                                    a0, a1, a2, a3, b0, b1);
                }
            }
        }
        __syncthreads();

        if (hasNext) {
            #pragma unroll
            for (int i = 0; i < 4; i++) {
                int idx = tid + i * 256;
                int r = idx >> 4, d4 = idx & 15;
                float* dk = sA + r * AP + d4 * 4;
                dk[0]=tf32_rna(pk[i].x); dk[1]=tf32_rna(pk[i].y);
                dk[2]=tf32_rna(pk[i].z); dk[3]=tf32_rna(pk[i].w);
                sB[(d4*4+0)*AP + r] = tf32_rna(pv[i].x);
                sB[(d4*4+1)*AP + r] = tf32_rna(pv[i].y);
                sB[(d4*4+2)*AP + r] = tf32_rna(pv[i].z);
                sB[(d4*4+3)*AP + r] = tf32_rna(pv[i].w);
            }
            __syncthreads();
        }
    }

    const float inv0 = 1.f / l0, inv1 = 1.f / l1;
    #pragma unroll
    for (int j2 = 0; j2 < 8; j2++) {
        int col = j2 * 8 + 2 * cq;
        float2 v0 = make_float2(of[j2][0] * inv0, of[j2][1] * inv0);
        float2 v1 = make_float2(of[j2][2] * inv1, of[j2][3] * inv1);
        *reinterpret_cast<float2*>(&Ob[(size_t)rowg0 * D_MODEL + col]) = v0;
        *reinterpret_cast<float2*>(&Ob[(size_t)rowg1 * D_MODEL + col]) = v1;
    }
}

// ---------------------------------------------------------------------------
// Launch
// ---------------------------------------------------------------------------
extern "C" void kernel_launch(void* const* d_in, const int* in_sizes, int n_in,
                              void* d_out, int out_size)
{
    (void)in_sizes; (void)n_in; (void)out_size;
    const float* q    = (const float*)d_in[0];
    const float* k    = (const float*)d_in[1];
    const float* v    = (const float*)d_in[2];
    // d_in[3] = mask (causal tril) — analytic
    const float* wq_w = (const float*)d_in[4];
    const float* wq_b = (const float*)d_in[5];
    const float* wk_w = (const float*)d_in[6];
    const float* wk_b = (const float*)d_in[7];
    const float* wv_w = (const float*)d_in[8];
    const float* wv_b = (const float*)d_in[9];
    const float* wo_w = (const float*)d_in[10];
    const float* wo_b = (const float*)d_in[11];
    float* out = (float*)d_out;

    void *pQ, *pK, *pV, *pC;
    cudaGetSymbolAddress(&pQ, g_Q);
    cudaGetSymbolAddress(&pK, g_K);
    cudaGetSymbolAddress(&pV, g_V);
    cudaGetSymbolAddress(&pC, g_ctx);
    float* Qp = (float*)pQ;
    float* Kp = (float*)pK;
    float* Vp = (float*)pV;
    float* Cp = (float*)pC;

    cudaFuncSetAttribute(gemm_tf32_qkv,
                         cudaFuncAttributeMaxDynamicSharedMemorySize, GEMM_SMEM_BYTES);
    cudaFuncSetAttribute(gemm_tf32_mma,
                         cudaFuncAttributeMaxDynamicSharedMemorySize, GEMM_SMEM_BYTES);

    dim3 qkvGrid(D_MODEL / BN, M_TOTAL / BM, 3);   // (8, 32, 3) = 768 CTAs
    gemm_tf32_qkv<<<qkvGrid, 256, GEMM_SMEM_BYTES>>>(q, k, v, wq_w, wk_w, wv_w,
                                                     wq_b, wk_b, wv_b, Qp, Kp, Vp);

    dim3 attnGrid(SEQ / AQ, HEADS, BATCH);         // (16, 16, 2)
    flash_attn_tc<<<attnGrid, 256>>>(Qp, Kp, Vp, Cp);

    dim3 gemmGrid(D_MODEL / BN, M_TOTAL / BM);     // (8, 32)
    gemm_tf32_mma<<<gemmGrid, 256, GEMM_SMEM_BYTES>>>(Cp, wo_w, wo_b, out,
                                                      M_TOTAL, D_MODEL, D_MODEL);
}